// round 16
// baseline (speedup 1.0000x reference)
#include <cuda_runtime.h>
#include <cuda_fp16.h>
#include <cstdint>
#include <cstddef>

#define NN 2048
#define NROWS 16384   // B * N

// ---------------- device scratch ----------------
__device__ __align__(128) float  g_dinv[NROWS];            // rsqrt(rowsum(A)+1)
__device__ __align__(128) __half g_Ah[(size_t)NROWS * NN]; // fp16 copy of A (64MB)
__device__ __align__(128) float  g_M1[NROWS * 64];         // d_j*(X@W1), f32 row-major
__device__ __align__(128) __half g_M1T[8 * 64 * NN];       // fp16 n-major M1 [b][64][2048]
__device__ __align__(128) float  g_Pp[NROWS * 16];         // d_j*(h_drop@W2), f32 row-major
__device__ __align__(128) __half g_PpT[8 * 16 * NN];       // fp16 n-major Pp [b][16][2048]

// ---------------- helpers ----------------
__device__ __forceinline__ uint32_t smem_u32(const void* p) {
    uint32_t a;
    asm("{ .reg .u64 t; cvta.to.shared.u64 t, %1; cvt.u32.u64 %0, t; }" : "=r"(a) : "l"(p));
    return a;
}
__device__ __forceinline__ void cp16(uint32_t dst, const void* src) {
    asm volatile("cp.async.cg.shared.global [%0], [%1], 16;" :: "r"(dst), "l"(src) : "memory");
}
__device__ __forceinline__ void mma_f16(float* c, const uint32_t* a, const uint32_t* b) {
    asm volatile("mma.sync.aligned.m16n8k16.row.col.f32.f16.f16.f32 "
                 "{%0,%1,%2,%3}, {%4,%5,%6,%7}, {%8,%9}, {%0,%1,%2,%3};"
                 : "+f"(c[0]), "+f"(c[1]), "+f"(c[2]), "+f"(c[3])
                 : "r"(a[0]), "r"(a[1]), "r"(a[2]), "r"(a[3]), "r"(b[0]), "r"(b[1]));
}

// ---------------- exact JAX threefry2x32 (partitionable), key = (0, 42) ----------------
__device__ __forceinline__ unsigned tf_rotl(unsigned x, int r) { return (x << r) | (x >> (32 - r)); }
__device__ __forceinline__ void threefry(unsigned x0, unsigned x1, unsigned &o0, unsigned &o1) {
    const unsigned k0 = 0u, k1 = 42u;
    const unsigned k2 = 0x1BD11BDAu ^ k0 ^ k1;
    x0 += k0; x1 += k1;
#define RND(r) { x0 += x1; x1 = tf_rotl(x1, (r)); x1 ^= x0; }
    RND(13) RND(15) RND(26) RND(6)   x0 += k1; x1 += k2 + 1u;
    RND(17) RND(29) RND(16) RND(24)  x0 += k2; x1 += k0 + 2u;
    RND(13) RND(15) RND(26) RND(6)   x0 += k0; x1 += k1 + 3u;
    RND(17) RND(29) RND(16) RND(24)  x0 += k1; x1 += k2 + 4u;
    RND(13) RND(15) RND(26) RND(6)   x0 += k2; x1 += k0 + 5u;
#undef RND
    o0 = x0; o1 = x1;
}

// ---------------- K1: d = rsqrt(rowsum+1) AND g_Ah = fp16(A) ----------------
__global__ __launch_bounds__(256) void k1_prep(const float* __restrict__ A) {
    int row  = blockIdx.x * 8 + (threadIdx.x >> 5);
    int lane = threadIdx.x & 31;
    const float4* p = reinterpret_cast<const float4*>(A + (size_t)row * NN);
    uint2* q = reinterpret_cast<uint2*>(g_Ah + (size_t)row * NN);
    float s = 0.f;
#pragma unroll
    for (int it = 0; it < 16; ++it) {
        float4 v = p[it * 32 + lane];
        s += (v.x + v.y) + (v.z + v.w);
        __half2 h0 = __floats2half2_rn(v.x, v.y);
        __half2 h1 = __floats2half2_rn(v.z, v.w);
        uint2 w;
        w.x = *reinterpret_cast<uint32_t*>(&h0);
        w.y = *reinterpret_cast<uint32_t*>(&h1);
        q[it * 32 + lane] = w;
    }
#pragma unroll
    for (int o = 16; o; o >>= 1) s += __shfl_xor_sync(0xffffffffu, s, o);
    if (lane == 0) g_dinv[row] = rsqrtf(s + 1.0f);
}

// ---------------- K2: M1 = d*(X@W1) -> f32 row-major + fp16 n-major ----------------
__global__ __launch_bounds__(256) void k2_xw(const float* __restrict__ X,
                                             const float* __restrict__ W1) {
    __shared__ __align__(16) float Ws[64][64];
    __shared__ float Xs[16][68];
    int tid  = threadIdx.x;
    int row0 = blockIdx.x * 16;
#pragma unroll
    for (int s = 0; s < 4; ++s) {
        int slot = tid + s * 256;
        *reinterpret_cast<float4*>(&Ws[0][0] + (size_t)slot * 4) =
            reinterpret_cast<const float4*>(W1)[slot];
    }
    {
        int r = tid >> 4, cq = tid & 15;
        float4 v = reinterpret_cast<const float4*>(X + (size_t)(row0 + r) * 64)[cq];
        Xs[r][cq * 4 + 0] = v.x; Xs[r][cq * 4 + 1] = v.y;
        Xs[r][cq * 4 + 2] = v.z; Xs[r][cq * 4 + 3] = v.w;
    }
    __syncthreads();
    int r = tid >> 4, cx = tid & 15;
    float4 acc = make_float4(0.f, 0.f, 0.f, 0.f);
#pragma unroll
    for (int k = 0; k < 64; ++k) {
        float x  = Xs[r][k];
        float4 w = *reinterpret_cast<const float4*>(&Ws[k][cx * 4]);
        acc.x = fmaf(x, w.x, acc.x);
        acc.y = fmaf(x, w.y, acc.y);
        acc.z = fmaf(x, w.z, acc.z);
        acc.w = fmaf(x, w.w, acc.w);
    }
    int grow = row0 + r;
    float d  = g_dinv[grow];
    acc.x *= d; acc.y *= d; acc.z *= d; acc.w *= d;
    reinterpret_cast<float4*>(g_M1 + (size_t)grow * 64)[cx] = acc;
    int bT = grow >> 11, rl = grow & 2047;
    g_M1T[((size_t)bT * 64 + cx * 4 + 0) * NN + rl] = __float2half_rn(acc.x);
    g_M1T[((size_t)bT * 64 + cx * 4 + 1) * NN + rl] = __float2half_rn(acc.y);
    g_M1T[((size_t)bT * 64 + cx * 4 + 2) * NN + rl] = __float2half_rn(acc.z);
    g_M1T[((size_t)bT * 64 + cx * 4 + 3) * NN + rl] = __float2half_rn(acc.w);
}

// ================= GEMM1 (R12-proven): 128-row tiles, 256 thr, 8 stages =================
// B=g_M1T; fused epilogue: h=relu(d*(acc+M1)+b1), threefry dropout,
// Pp -> g_Pp (f32) + g_PpT (fp16 n-major).
__global__ __launch_bounds__(256) void gemm1(const float* __restrict__ b1g,
                                             const float* __restrict__ W2g) {
    constexpr int NSTAGE = 8;
    constexpr int STR = 72;
    constexpr int ASTAGEH = 128 * STR;
    constexpr int BSTAGEH = 64 * STR;
    extern __shared__ __align__(16) __half smemh[];
    __half* Abase = smemh;
    __half* Bbase = smemh + NSTAGE * ASTAGEH;

    const int tid = threadIdx.x, wid = tid >> 5, lane = tid & 31;
    const int wm = wid & 3, wn = wid >> 2;        // warp: rows wm*32, cols wn*32
    const int bb = blockIdx.y, row0 = blockIdx.x << 7;
    const __half* Ab = g_Ah + ((size_t)bb * NN + row0) * NN;
    const __half* Bb = g_M1T + (size_t)bb * 64 * NN;
    const uint32_t sb = smem_u32(smemh);

    float acc[2][4][4];
#pragma unroll
    for (int i = 0; i < 2; ++i)
#pragma unroll
        for (int j = 0; j < 4; ++j)
#pragma unroll
            for (int q = 0; q < 4; ++q) acc[i][j][q] = 0.f;

    auto load_chunk = [&](int c, int s) {
        uint32_t ab = sb + s * (ASTAGEH * 2);
#pragma unroll
        for (int j = 0; j < 4; ++j) {
            int seg = tid + j * 256;
            int r = seg >> 3, q = seg & 7;
            cp16(ab + (uint32_t)(r * STR * 2 + q * 16), Ab + (size_t)r * NN + c * 64 + q * 8);
        }
        uint32_t bbs = sb + (uint32_t)(NSTAGE * ASTAGEH * 2) + s * (BSTAGEH * 2);
#pragma unroll
        for (int j = 0; j < 2; ++j) {
            int seg = tid + j * 256;
            int n = seg >> 3, q = seg & 7;
            cp16(bbs + (uint32_t)(n * STR * 2 + q * 16), Bb + (size_t)n * NN + c * 64 + q * 8);
        }
        asm volatile("cp.async.commit_group;" ::: "memory");
    };

#pragma unroll
    for (int c = 0; c < 7; ++c) load_chunk(c, c);

    const int arow = lane >> 2, acol = lane & 3;
    int s_comp = 0, s_load = 7;
#pragma unroll 1
    for (int i = 0; i < 32; ++i) {
        asm volatile("cp.async.wait_group 6;" ::: "memory");
        __syncthreads();
        if (i < 25) load_chunk(i + 7, s_load);
        else        asm volatile("cp.async.commit_group;" ::: "memory");
        const __half* As = Abase + s_comp * ASTAGEH;
        const __half* Bs = Bbase + s_comp * BSTAGEH;
#pragma unroll
        for (int ks = 0; ks < 4; ++ks) {
            int kh = ks * 16 + 2 * acol;
            uint32_t af[2][4];
#pragma unroll
            for (int mi = 0; mi < 2; ++mi) {
                int r = wm * 32 + mi * 16 + arow;
                af[mi][0] = *reinterpret_cast<const uint32_t*>(&As[r * STR + kh]);
                af[mi][1] = *reinterpret_cast<const uint32_t*>(&As[(r + 8) * STR + kh]);
                af[mi][2] = *reinterpret_cast<const uint32_t*>(&As[r * STR + kh + 8]);
                af[mi][3] = *reinterpret_cast<const uint32_t*>(&As[(r + 8) * STR + kh + 8]);
            }
            uint32_t bf[4][2];
#pragma unroll
            for (int ni = 0; ni < 4; ++ni) {
                int n = wn * 32 + ni * 8 + arow;
                bf[ni][0] = *reinterpret_cast<const uint32_t*>(&Bs[n * STR + kh]);
                bf[ni][1] = *reinterpret_cast<const uint32_t*>(&Bs[n * STR + kh + 8]);
            }
#pragma unroll
            for (int mi = 0; mi < 2; ++mi)
#pragma unroll
                for (int ni = 0; ni < 4; ++ni)
                    mma_f16(acc[mi][ni], af[mi], bf[ni]);
        }
        if (++s_comp == NSTAGE) s_comp = 0;
        if (++s_load == NSTAGE) s_load = 0;
    }

    // ---- fused epilogue ----
    constexpr int HSTR = 66;
    float* hs  = reinterpret_cast<float*>(smemh);   // [128][66]
    float* W2s = hs + 128 * HSTR;                   // [64][16]
    __syncthreads();
    reinterpret_cast<float4*>(W2s)[tid] = reinterpret_cast<const float4*>(W2g)[tid];
#pragma unroll
    for (int mi = 0; mi < 2; ++mi) {
#pragma unroll
        for (int h = 0; h < 2; ++h) {
            int r = wm * 32 + mi * 16 + arow + h * 8;
            size_t grow = (size_t)bb * NN + row0 + r;
            float dv = g_dinv[grow];
#pragma unroll
            for (int ni = 0; ni < 4; ++ni) {
                int c = wn * 32 + ni * 8 + acol * 2;
#pragma unroll
                for (int e = 0; e < 2; ++e) {
                    float val = acc[mi][ni][h * 2 + e];
                    float pre = dv * (val + g_M1[grow * 64 + c + e]) + b1g[c + e];
                    float hh  = fmaxf(pre, 0.0f);
                    unsigned idx = ((unsigned)grow << 6) + (unsigned)(c + e);
                    unsigned o0, o1;
                    threefry(0u, idx, o0, o1);
                    hs[r * HSTR + c + e] = ((o0 ^ o1) & 0x80000000u) ? 0.0f : hh + hh;
                }
            }
        }
    }
    __syncthreads();
    int r2 = tid >> 1, cg = (tid & 1) * 8;
    float a8[8] = {0.f, 0.f, 0.f, 0.f, 0.f, 0.f, 0.f, 0.f};
#pragma unroll
    for (int k = 0; k < 64; ++k) {
        float hv = hs[r2 * HSTR + k];
        float4 w0 = *reinterpret_cast<const float4*>(&W2s[k * 16 + cg]);
        float4 w1 = *reinterpret_cast<const float4*>(&W2s[k * 16 + cg + 4]);
        a8[0] = fmaf(hv, w0.x, a8[0]); a8[1] = fmaf(hv, w0.y, a8[1]);
        a8[2] = fmaf(hv, w0.z, a8[2]); a8[3] = fmaf(hv, w0.w, a8[3]);
        a8[4] = fmaf(hv, w1.x, a8[4]); a8[5] = fmaf(hv, w1.y, a8[5]);
        a8[6] = fmaf(hv, w1.z, a8[6]); a8[7] = fmaf(hv, w1.w, a8[7]);
    }
    size_t grow2 = (size_t)bb * NN + row0 + r2;
    float dv2 = g_dinv[grow2];
#pragma unroll
    for (int j = 0; j < 8; ++j) a8[j] *= dv2;
    *reinterpret_cast<float4*>(&g_Pp[grow2 * 16 + cg])     = make_float4(a8[0], a8[1], a8[2], a8[3]);
    *reinterpret_cast<float4*>(&g_Pp[grow2 * 16 + cg + 4]) = make_float4(a8[4], a8[5], a8[6], a8[7]);
    int rl = (int)(grow2 & 2047);
#pragma unroll
    for (int j = 0; j < 8; ++j)
        g_PpT[((size_t)bb * 16 + cg + j) * NN + rl] = __float2half_rn(a8[j]);
}

// ================= GEMM2: 64-row tiles (2 CTAs/SM), 256 thr, 6 stages =================
// out = d*(A@Pp + Pp) + b2.  Warp = 16 rows x 8 cols (wm=wid&3, wn=wid>>2).
__global__ __launch_bounds__(256) void gemm2(const float* __restrict__ b2,
                                             float* __restrict__ out) {
    constexpr int NSTAGE = 6;
    constexpr int STR = 72;
    constexpr int ASTAGEH = 64 * STR;             // 4608 halves
    constexpr int BSTAGEH = 16 * STR;             // 1152 halves
    extern __shared__ __align__(16) __half smemh[];
    __half* Abase = smemh;
    __half* Bbase = smemh + NSTAGE * ASTAGEH;

    const int tid = threadIdx.x, wid = tid >> 5, lane = tid & 31;
    const int wm = wid & 3, wn = wid >> 2;        // warp: rows wm*16, cols wn*8
    const int bb = blockIdx.y, row0 = blockIdx.x << 6;
    const __half* Ab = g_Ah + ((size_t)bb * NN + row0) * NN;
    const __half* Bb = g_PpT + (size_t)bb * 16 * NN;
    const uint32_t sb = smem_u32(smemh);

    float acc[4] = {0.f, 0.f, 0.f, 0.f};

    auto load_chunk = [&](int c, int s) {
        uint32_t ab = sb + s * (ASTAGEH * 2);
#pragma unroll
        for (int j = 0; j < 2; ++j) {             // 512 cp16: 64 rows x 128B
            int seg = tid + j * 256;
            int r = seg >> 3, q = seg & 7;
            cp16(ab + (uint32_t)(r * STR * 2 + q * 16), Ab + (size_t)r * NN + c * 64 + q * 8);
        }
        uint32_t bbs = sb + (uint32_t)(NSTAGE * ASTAGEH * 2) + s * (BSTAGEH * 2);
        if (tid < 128) {                          // 128 cp16: 16 n-rows x 128B
            int n = tid >> 3, q = tid & 7;
            cp16(bbs + (uint32_t)(n * STR * 2 + q * 16), Bb + (size_t)n * NN + c * 64 + q * 8);
        }
        asm volatile("cp.async.commit_group;" ::: "memory");
    };

#pragma unroll
    for (int c = 0; c < 5; ++c) load_chunk(c, c);

    const int arow = lane >> 2, acol = lane & 3;
    int s_comp = 0, s_load = 5;
#pragma unroll 1
    for (int i = 0; i < 32; ++i) {
        asm volatile("cp.async.wait_group 4;" ::: "memory");
        __syncthreads();
        if (i < 27) load_chunk(i + 5, s_load);
        else        asm volatile("cp.async.commit_group;" ::: "memory");
        const __half* As = Abase + s_comp * ASTAGEH;
        const __half* Bs = Bbase + s_comp * BSTAGEH;
#pragma unroll
        for (int ks = 0; ks < 4; ++ks) {
            int kh = ks * 16 + 2 * acol;
            int r = wm * 16 + arow;
            uint32_t af[4];
            af[0] = *reinterpret_cast<const uint32_t*>(&As[r * STR + kh]);
            af[1] = *reinterpret_cast<const uint32_t*>(&As[(r + 8) * STR + kh]);
            af[2] = *reinterpret_cast<const uint32_t*>(&As[r * STR + kh + 8]);
            af[3] = *reinterpret_cast<const uint32_t*>(&As[(r + 8) * STR + kh + 8]);
            int n = wn * 8 + arow;
            uint32_t bf[2];
            bf[0] = *reinterpret_cast<const uint32_t*>(&Bs[n * STR + kh]);
            bf[1] = *reinterpret_cast<const uint32_t*>(&Bs[n * STR + kh + 8]);
            mma_f16(acc, af, bf);
        }
        if (++s_comp == NSTAGE) s_comp = 0;
        if (++s_load == NSTAGE) s_load = 0;
    }

    // ---- epilogue: out = d*(acc + Pp) + b2 ----
#pragma unroll
    for (int h = 0; h < 2; ++h) {
        int r = wm * 16 + arow + h * 8;
        int c = wn * 8 + acol * 2;
        float v0 = acc[h * 2 + 0];
        float v1 = acc[h * 2 + 1];
        size_t grow = (size_t)bb * NN + row0 + r;
        float dv = g_dinv[grow];
        float p0 = g_Pp[grow * 16 + c];
        float p1 = g_Pp[grow * 16 + c + 1];
        float2 o;
        o.x = dv * (v0 + p0) + b2[c];
        o.y = dv * (v1 + p1) + b2[c + 1];
        *reinterpret_cast<float2*>(out + grow * 16 + c) = o;
    }
}

// ---------------- launch ----------------
extern "C" void kernel_launch(void* const* d_in, const int* in_sizes, int n_in,
                              void* d_out, int out_size) {
    const float* X  = (const float*)d_in[0];
    const float* A  = (const float*)d_in[1];
    const float* W1 = (const float*)d_in[2];
    const float* b1 = (const float*)d_in[3];
    const float* W2 = (const float*)d_in[4];
    const float* b2 = (const float*)d_in[5];
    float* out = (float*)d_out;

    const int SM1 = 8 * (128 + 64) * 72 * 2;   // 221184 B
    const int SM2 = 6 * (64 + 16) * 72 * 2;    //  69120 B -> 2+ CTAs/SM
    cudaFuncSetAttribute((const void*)gemm1, cudaFuncAttributeMaxDynamicSharedMemorySize, SM1);
    cudaFuncSetAttribute((const void*)gemm2, cudaFuncAttributeMaxDynamicSharedMemorySize, SM2);

    k1_prep<<<2048, 256>>>(A);
    k2_xw<<<1024, 256>>>(X, W1);
    gemm1<<<dim3(16, 8), 256, SM1>>>(b1, W2);
    gemm2<<<dim3(32, 8), 256, SM2>>>(b2, out);
}

// round 17
// speedup vs baseline: 1.4605x; 1.4605x over previous
#include <cuda_runtime.h>
#include <cuda_fp16.h>
#include <cstdint>
#include <cstddef>

#define NN 2048
#define NROWS 16384   // B * N

// ---------------- device scratch ----------------
__device__ __align__(128) float  g_dinv[NROWS];            // rsqrt(rowsum(A)+1)
__device__ __align__(128) __half g_Ah[(size_t)NROWS * NN]; // fp16 copy of A (64MB)
__device__ __align__(128) float  g_M1[NROWS * 64];         // d_j*(X@W1), f32 row-major
__device__ __align__(128) __half g_M1T[8 * 64 * NN];       // fp16 n-major M1 [b][64][2048]
__device__ __align__(128) float  g_Pp[NROWS * 16];         // d_j*(h_drop@W2), f32 row-major
__device__ __align__(128) __half g_PpT[8 * 16 * NN];       // fp16 n-major Pp [b][16][2048]

// ---------------- helpers ----------------
__device__ __forceinline__ uint32_t smem_u32(const void* p) {
    uint32_t a;
    asm("{ .reg .u64 t; cvta.to.shared.u64 t, %1; cvt.u32.u64 %0, t; }" : "=r"(a) : "l"(p));
    return a;
}
__device__ __forceinline__ void cp16(uint32_t dst, const void* src) {
    asm volatile("cp.async.cg.shared.global [%0], [%1], 16;" :: "r"(dst), "l"(src) : "memory");
}
__device__ __forceinline__ void mma_f16(float* c, const uint32_t* a, const uint32_t* b) {
    asm volatile("mma.sync.aligned.m16n8k16.row.col.f32.f16.f16.f32 "
                 "{%0,%1,%2,%3}, {%4,%5,%6,%7}, {%8,%9}, {%0,%1,%2,%3};"
                 : "+f"(c[0]), "+f"(c[1]), "+f"(c[2]), "+f"(c[3])
                 : "r"(a[0]), "r"(a[1]), "r"(a[2]), "r"(a[3]), "r"(b[0]), "r"(b[1]));
}

// ---------------- exact JAX threefry2x32 (partitionable), key = (0, 42) ----------------
__device__ __forceinline__ unsigned tf_rotl(unsigned x, int r) { return (x << r) | (x >> (32 - r)); }
__device__ __forceinline__ void threefry(unsigned x0, unsigned x1, unsigned &o0, unsigned &o1) {
    const unsigned k0 = 0u, k1 = 42u;
    const unsigned k2 = 0x1BD11BDAu ^ k0 ^ k1;
    x0 += k0; x1 += k1;
#define RND(r) { x0 += x1; x1 = tf_rotl(x1, (r)); x1 ^= x0; }
    RND(13) RND(15) RND(26) RND(6)   x0 += k1; x1 += k2 + 1u;
    RND(17) RND(29) RND(16) RND(24)  x0 += k2; x1 += k0 + 2u;
    RND(13) RND(15) RND(26) RND(6)   x0 += k0; x1 += k1 + 3u;
    RND(17) RND(29) RND(16) RND(24)  x0 += k1; x1 += k2 + 4u;
    RND(13) RND(15) RND(26) RND(6)   x0 += k2; x1 += k0 + 5u;
#undef RND
    o0 = x0; o1 = x1;
}

// ---------------- K1: d = rsqrt(rowsum+1) AND g_Ah = fp16(A) ----------------
__global__ __launch_bounds__(256) void k1_prep(const float* __restrict__ A) {
    int row  = blockIdx.x * 8 + (threadIdx.x >> 5);
    int lane = threadIdx.x & 31;
    const float4* p = reinterpret_cast<const float4*>(A + (size_t)row * NN);
    uint2* q = reinterpret_cast<uint2*>(g_Ah + (size_t)row * NN);
    float s = 0.f;
#pragma unroll
    for (int it = 0; it < 16; ++it) {
        float4 v = p[it * 32 + lane];
        s += (v.x + v.y) + (v.z + v.w);
        __half2 h0 = __floats2half2_rn(v.x, v.y);
        __half2 h1 = __floats2half2_rn(v.z, v.w);
        uint2 w;
        w.x = *reinterpret_cast<uint32_t*>(&h0);
        w.y = *reinterpret_cast<uint32_t*>(&h1);
        q[it * 32 + lane] = w;
    }
#pragma unroll
    for (int o = 16; o; o >>= 1) s += __shfl_xor_sync(0xffffffffu, s, o);
    if (lane == 0) g_dinv[row] = rsqrtf(s + 1.0f);
}

// ---------------- K2: M1 = d*(X@W1) -> f32 row-major + fp16 n-major ----------------
__global__ __launch_bounds__(256) void k2_xw(const float* __restrict__ X,
                                             const float* __restrict__ W1) {
    __shared__ __align__(16) float Ws[64][64];
    __shared__ float Xs[16][68];
    int tid  = threadIdx.x;
    int row0 = blockIdx.x * 16;
#pragma unroll
    for (int s = 0; s < 4; ++s) {
        int slot = tid + s * 256;
        *reinterpret_cast<float4*>(&Ws[0][0] + (size_t)slot * 4) =
            reinterpret_cast<const float4*>(W1)[slot];
    }
    {
        int r = tid >> 4, cq = tid & 15;
        float4 v = reinterpret_cast<const float4*>(X + (size_t)(row0 + r) * 64)[cq];
        Xs[r][cq * 4 + 0] = v.x; Xs[r][cq * 4 + 1] = v.y;
        Xs[r][cq * 4 + 2] = v.z; Xs[r][cq * 4 + 3] = v.w;
    }
    __syncthreads();
    int r = tid >> 4, cx = tid & 15;
    float4 acc = make_float4(0.f, 0.f, 0.f, 0.f);
#pragma unroll
    for (int k = 0; k < 64; ++k) {
        float x  = Xs[r][k];
        float4 w = *reinterpret_cast<const float4*>(&Ws[k][cx * 4]);
        acc.x = fmaf(x, w.x, acc.x);
        acc.y = fmaf(x, w.y, acc.y);
        acc.z = fmaf(x, w.z, acc.z);
        acc.w = fmaf(x, w.w, acc.w);
    }
    int grow = row0 + r;
    float d  = g_dinv[grow];
    acc.x *= d; acc.y *= d; acc.z *= d; acc.w *= d;
    reinterpret_cast<float4*>(g_M1 + (size_t)grow * 64)[cx] = acc;
    int bT = grow >> 11, rl = grow & 2047;
    g_M1T[((size_t)bT * 64 + cx * 4 + 0) * NN + rl] = __float2half_rn(acc.x);
    g_M1T[((size_t)bT * 64 + cx * 4 + 1) * NN + rl] = __float2half_rn(acc.y);
    g_M1T[((size_t)bT * 64 + cx * 4 + 2) * NN + rl] = __float2half_rn(acc.z);
    g_M1T[((size_t)bT * 64 + cx * 4 + 3) * NN + rl] = __float2half_rn(acc.w);
}

// ---------------- fp16 mma GEMM: 128-row tiles, 256 thr, 4 stages, k-chunk = 128 ----------------
// Chunk = 128 halves (256B/row): 16 chunks total -> half the per-chunk sync overhead of R12.
// NCOLS=64, FINAL=false: B=g_M1T; fused epilogue: h=relu(d*(acc+M1)+b1), threefry
//   dropout, Pp -> g_Pp (f32) + g_PpT (fp16 n-major).
// NCOLS=16, FINAL=true : B=g_PpT; epilogue out = d*(acc+Pp)+b2 -> out.
template<int NCOLS, bool FINAL>
__global__ __launch_bounds__(256) void gemm_mma(const float* __restrict__ b1g,
                                                const float* __restrict__ W2g,
                                                const float* __restrict__ b2,
                                                float* __restrict__ out) {
    constexpr int NSTAGE = 4;
    constexpr int STR = 136;                      // smem stride in halves (272B)
    constexpr int ASTAGEH = 128 * STR;            // 17408 halves
    constexpr int BSTAGEH = NCOLS * STR;
    extern __shared__ __align__(16) __half smemh[];
    __half* Abase = smemh;
    __half* Bbase = smemh + NSTAGE * ASTAGEH;

    const int tid = threadIdx.x, wid = tid >> 5, lane = tid & 31;
    const int wm = wid & 3, wn = wid >> 2;        // warp: rows wm*32 (2 x m16), cols wn*(NCOLS/2)
    const int bb = blockIdx.y, row0 = blockIdx.x << 7;
    const __half* Ab = g_Ah + ((size_t)bb * NN + row0) * NN;
    const __half* Bb = (FINAL ? g_PpT : g_M1T) + (size_t)bb * NCOLS * NN;
    const uint32_t sb = smem_u32(smemh);

    constexpr int NMMA = NCOLS / 16;              // 4 or 1
    float acc[2][NMMA][4];
#pragma unroll
    for (int i = 0; i < 2; ++i)
#pragma unroll
        for (int j = 0; j < NMMA; ++j)
#pragma unroll
            for (int q = 0; q < 4; ++q) acc[i][j][q] = 0.f;

    auto load_chunk = [&](int c, int s) {
        uint32_t ab = sb + s * (ASTAGEH * 2);
#pragma unroll
        for (int j = 0; j < 8; ++j) {             // 2048 cp16: 128 rows x 256B
            int seg = tid + j * 256;
            int r = seg >> 4, q = seg & 15;
            cp16(ab + (uint32_t)(r * STR * 2 + q * 16), Ab + (size_t)r * NN + c * 128 + q * 8);
        }
        uint32_t bbs = sb + (uint32_t)(NSTAGE * ASTAGEH * 2) + s * (BSTAGEH * 2);
        if (NCOLS == 64) {
#pragma unroll
            for (int j = 0; j < 4; ++j) {         // 1024 cp16: 64 n-rows x 256B
                int seg = tid + j * 256;
                int n = seg >> 4, q = seg & 15;
                cp16(bbs + (uint32_t)(n * STR * 2 + q * 16), Bb + (size_t)n * NN + c * 128 + q * 8);
            }
        } else {
            {                                      // 256 cp16: 16 n-rows x 256B
                int n = tid >> 4, q = tid & 15;
                cp16(bbs + (uint32_t)(n * STR * 2 + q * 16), Bb + (size_t)n * NN + c * 128 + q * 8);
            }
        }
        asm volatile("cp.async.commit_group;" ::: "memory");
    };

    // prologue: 3 of 16 chunks ahead
#pragma unroll
    for (int c = 0; c < 3; ++c) load_chunk(c, c);

    const int arow = lane >> 2, acol = lane & 3;
    int s_comp = 0, s_load = 3;
#pragma unroll 1
    for (int i = 0; i < 16; ++i) {
        asm volatile("cp.async.wait_group 2;" ::: "memory");   // chunk i resident
        __syncthreads();                                       // stage s_load's old readers done
        if (i < 13) load_chunk(i + 3, s_load);
        else        asm volatile("cp.async.commit_group;" ::: "memory");
        const __half* As = Abase + s_comp * ASTAGEH;
        const __half* Bs = Bbase + s_comp * BSTAGEH;
#pragma unroll
        for (int ks = 0; ks < 8; ++ks) {          // 8 x k16 per chunk
            int kh = ks * 16 + 2 * acol;          // half index within chunk
            uint32_t af[2][4];
#pragma unroll
            for (int mi = 0; mi < 2; ++mi) {
                int r = wm * 32 + mi * 16 + arow;
                af[mi][0] = *reinterpret_cast<const uint32_t*>(&As[r * STR + kh]);
                af[mi][1] = *reinterpret_cast<const uint32_t*>(&As[(r + 8) * STR + kh]);
                af[mi][2] = *reinterpret_cast<const uint32_t*>(&As[r * STR + kh + 8]);
                af[mi][3] = *reinterpret_cast<const uint32_t*>(&As[(r + 8) * STR + kh + 8]);
            }
            uint32_t bf[NMMA][2];
#pragma unroll
            for (int ni = 0; ni < NMMA; ++ni) {
                int n = wn * (NCOLS / 2) + ni * 8 + arow;
                bf[ni][0] = *reinterpret_cast<const uint32_t*>(&Bs[n * STR + kh]);
                bf[ni][1] = *reinterpret_cast<const uint32_t*>(&Bs[n * STR + kh + 8]);
            }
#pragma unroll
            for (int mi = 0; mi < 2; ++mi)
#pragma unroll
                for (int ni = 0; ni < NMMA; ++ni)
                    mma_f16(acc[mi][ni], af[mi], bf[ni]);
        }
        if (++s_comp == NSTAGE) s_comp = 0;
        if (++s_load == NSTAGE) s_load = 0;
    }

    // ---------------- epilogues ----------------
    if (FINAL) {
#pragma unroll
        for (int mi = 0; mi < 2; ++mi) {
#pragma unroll
            for (int ni = 0; ni < NMMA; ++ni) {
#pragma unroll
                for (int h = 0; h < 2; ++h) {
                    int r = wm * 32 + mi * 16 + arow + h * 8;
                    int c = wn * (NCOLS / 2) + ni * 8 + acol * 2;
                    float v0 = acc[mi][ni][h * 2 + 0];
                    float v1 = acc[mi][ni][h * 2 + 1];
                    size_t grow = (size_t)bb * NN + row0 + r;
                    float dv = g_dinv[grow];
                    float p0 = g_Pp[grow * 16 + c];
                    float p1 = g_Pp[grow * 16 + c + 1];
                    float2 o;
                    o.x = dv * (v0 + p0) + b2[c];
                    o.y = dv * (v1 + p1) + b2[c + 1];
                    *reinterpret_cast<float2*>(out + grow * 16 + c) = o;
                }
            }
        }
    } else {
        // fused layer-1 activation + dropout + (h @ W2) epilogue
        constexpr int HSTR = 66;
        float* hs  = reinterpret_cast<float*>(smemh);   // [128][66]
        float* W2s = hs + 128 * HSTR;                   // [64][16]
        __syncthreads();                                // pipeline reads done before overwrite
        reinterpret_cast<float4*>(W2s)[tid] = reinterpret_cast<const float4*>(W2g)[tid];
#pragma unroll
        for (int mi = 0; mi < 2; ++mi) {
#pragma unroll
            for (int h = 0; h < 2; ++h) {
                int r = wm * 32 + mi * 16 + arow + h * 8;
                size_t grow = (size_t)bb * NN + row0 + r;
                float dv = g_dinv[grow];
#pragma unroll
                for (int ni = 0; ni < NMMA; ++ni) {
                    int c = wn * 32 + ni * 8 + acol * 2;
#pragma unroll
                    for (int e = 0; e < 2; ++e) {
                        float val = acc[mi][ni][h * 2 + e];
                        float pre = dv * (val + g_M1[grow * 64 + c + e]) + b1g[c + e];
                        float hh  = fmaxf(pre, 0.0f);
                        unsigned idx = ((unsigned)grow << 6) + (unsigned)(c + e);
                        unsigned o0, o1;
                        threefry(0u, idx, o0, o1);
                        hs[r * HSTR + c + e] = ((o0 ^ o1) & 0x80000000u) ? 0.0f : hh + hh;
                    }
                }
            }
        }
        __syncthreads();
        // Pp = dinv*(hs@W2): thread -> (row = tid>>1, 8 cols); write f32 + fp16 n-major
        int r2 = tid >> 1, cg = (tid & 1) * 8;
        float a8[8] = {0.f, 0.f, 0.f, 0.f, 0.f, 0.f, 0.f, 0.f};
#pragma unroll
        for (int k = 0; k < 64; ++k) {
            float hv = hs[r2 * HSTR + k];
            float4 w0 = *reinterpret_cast<const float4*>(&W2s[k * 16 + cg]);
            float4 w1 = *reinterpret_cast<const float4*>(&W2s[k * 16 + cg + 4]);
            a8[0] = fmaf(hv, w0.x, a8[0]); a8[1] = fmaf(hv, w0.y, a8[1]);
            a8[2] = fmaf(hv, w0.z, a8[2]); a8[3] = fmaf(hv, w0.w, a8[3]);
            a8[4] = fmaf(hv, w1.x, a8[4]); a8[5] = fmaf(hv, w1.y, a8[5]);
            a8[6] = fmaf(hv, w1.z, a8[6]); a8[7] = fmaf(hv, w1.w, a8[7]);
        }
        size_t grow2 = (size_t)bb * NN + row0 + r2;
        float dv2 = g_dinv[grow2];
#pragma unroll
        for (int j = 0; j < 8; ++j) a8[j] *= dv2;
        *reinterpret_cast<float4*>(&g_Pp[grow2 * 16 + cg])     = make_float4(a8[0], a8[1], a8[2], a8[3]);
        *reinterpret_cast<float4*>(&g_Pp[grow2 * 16 + cg + 4]) = make_float4(a8[4], a8[5], a8[6], a8[7]);
        int rl = (int)(grow2 & 2047);
#pragma unroll
        for (int j = 0; j < 8; ++j)
            g_PpT[((size_t)bb * 16 + cg + j) * NN + rl] = __float2half_rn(a8[j]);
    }
}

// ---------------- launch ----------------
extern "C" void kernel_launch(void* const* d_in, const int* in_sizes, int n_in,
                              void* d_out, int out_size) {
    const float* X  = (const float*)d_in[0];
    const float* A  = (const float*)d_in[1];
    const float* W1 = (const float*)d_in[2];
    const float* b1 = (const float*)d_in[3];
    const float* W2 = (const float*)d_in[4];
    const float* b2 = (const float*)d_in[5];
    float* out = (float*)d_out;

    const int SM64 = 4 * (128 + 64) * 136 * 2;   // 208896 B
    const int SM16 = 4 * (128 + 16) * 136 * 2;   // 156672 B
    cudaFuncSetAttribute((const void*)gemm_mma<64, false>,
                         cudaFuncAttributeMaxDynamicSharedMemorySize, SM64);
    cudaFuncSetAttribute((const void*)gemm_mma<16, true>,
                         cudaFuncAttributeMaxDynamicSharedMemorySize, SM16);

    k1_prep<<<2048, 256>>>(A);
    k2_xw<<<1024, 256>>>(X, W1);
    gemm_mma<64, false><<<dim3(16, 8), 256, SM64>>>(b1, W2, nullptr, nullptr);
    gemm_mma<16, true><<<dim3(16, 8), 256, SM16>>>(nullptr, nullptr, b2, out);
}